// round 2
// baseline (speedup 1.0000x reference)
#include <cuda_runtime.h>
#include <cstdint>

#define QV   32
#define NTOK 8192
#define HD   128
#define DD   64
#define RDIM 64
#define G3   384
#define NH   (NTOK*HD)   /* 1048576 */

typedef unsigned long long ull;

// ---------------- scratch (allocation-free) ----------------
__device__ float g_demb[NTOK*HD];       // 4 MB
__device__ float g_ws[QV*NTOK*HD];      // 128 MB
__device__ float g_hhat[QV*NTOK*HD];    // 128 MB
__device__ float g_cih[QV*G3];          // var_embed@W_ih + b_ih

// ---------------- f32x2 helpers ----------------
__device__ __forceinline__ ull pack2(float x) {
    ull r; unsigned xi = __float_as_uint(x);
    asm("mov.b64 %0, {%1, %1};" : "=l"(r) : "r"(xi));
    return r;
}
__device__ __forceinline__ float2 unpack2(ull v) {
    unsigned lo, hi;
    asm("mov.b64 {%0, %1}, %2;" : "=r"(lo), "=r"(hi) : "l"(v));
    return make_float2(__uint_as_float(lo), __uint_as_float(hi));
}
__device__ __forceinline__ void ffma2(ull &d, ull a, ull b) {
    asm("fma.rn.f32x2 %0, %1, %2, %0;" : "+l"(d) : "l"(a), "l"(b));
}
__device__ __forceinline__ float sigm(float x) { return 1.f / (1.f + __expf(-x)); }
__device__ __forceinline__ float tanh_fast(float x) {
    float a = fabsf(x);
    float e = __expf(-2.f * a);
    float t = (1.f - e) / (1.f + e);
    return copysignf(t, x);
}

// ---------------- setup: c_ih = var_embed @ W_ih^T + b_ih ; A_masked out ----------------
__global__ void k_setup(const float* __restrict__ A_dag, const float* __restrict__ Wih,
                        const float* __restrict__ bih, const float* __restrict__ ve,
                        float* __restrict__ outA) {
    int k = blockIdx.x, t = threadIdx.x;
    __shared__ float sve[HD];
    sve[t] = ve[k*HD + t];
    __syncthreads();
    for (int m = t; m < G3; m += 128) {
        const float* w = Wih + ((size_t)k*G3 + m)*HD;
        float acc = bih[k*G3 + m];
        #pragma unroll 8
        for (int j = 0; j < HD; j++) acc += sve[j] * w[j];
        g_cih[k*G3 + m] = acc;
    }
    if (k == 0) {
        for (int idx = t; idx < QV*QV; idx += 128) {
            int i = idx / QV, j = idx % QV;
            outA[idx] = (i == j) ? 0.f : A_dag[idx];
        }
    }
}

// ---------------- driver_emb = relu(driver @ driver_W + b) ----------------
__global__ void k_demb(const float* __restrict__ driver, const float* __restrict__ dW,
                       const float* __restrict__ db) {
    __shared__ float sdrv[8][DD];
    int n0 = blockIdx.x * 8, t = threadIdx.x;
    for (int i = t; i < 8*DD; i += 128)
        sdrv[i/DD][i%DD] = driver[(size_t)(n0 + i/DD)*DD + (i%DD)];
    __syncthreads();
    float acc[8];
    float b = db[t];
    #pragma unroll
    for (int r = 0; r < 8; r++) acc[r] = b;
    #pragma unroll 4
    for (int d = 0; d < DD; d++) {
        float w = dW[d*HD + t];
        #pragma unroll
        for (int r = 0; r < 8; r++) acc[r] += sdrv[r][d] * w;
    }
    #pragma unroll
    for (int r = 0; r < 8; r++)
        g_demb[(size_t)(n0 + r)*HD + t] = fmaxf(acc[r], 0.f);
}

// ---------------- ws[k,n,j] = sum_i A_masked[i,k] * H_prev[i,n,j] ----------------
__global__ __launch_bounds__(256) void k_ws(const float* __restrict__ Hp,
                                            const float* __restrict__ A_dag) {
    __shared__ ull sA[QV][QV];       // packed-duplicated A_masked[i][k]
    int t = threadIdx.x;
    for (int idx = t; idx < QV*QV; idx += 256) {
        int i = idx / QV, kk = idx % QV;
        float v = (i == kk) ? 0.f : A_dag[idx];
        sA[i][kk] = pack2(v);
    }
    __syncthreads();
    size_t p = ((size_t)blockIdx.x * 256 + t) * 2;
    ull acc[QV];
    #pragma unroll
    for (int kk = 0; kk < QV; kk++) acc[kk] = 0ull;
    #pragma unroll 4
    for (int i = 0; i < QV; i++) {
        ull h = *(const ull*)(Hp + (size_t)i*NH + p);
        #pragma unroll
        for (int kk = 0; kk < QV; kk++) ffma2(acc[kk], sA[i][kk], h);
    }
    #pragma unroll
    for (int kk = 0; kk < QV; kk++)
        *(ull*)(g_ws + (size_t)kk*NH + p) = acc[kk];
}

// ---------------- struct MLP: Hhat = (relu(WS@W1+b1))@W2 + b2, per k ----------------
// grid (128 ntiles of 64 rows, 32 k), 256 thr, dyn smem 192KB
__global__ __launch_bounds__(256, 1) void k_struct(const float* __restrict__ W1,
                                                   const float* __restrict__ b1,
                                                   const float* __restrict__ W2,
                                                   const float* __restrict__ b2) {
    const int n0 = blockIdx.x * 64;
    const int k  = blockIdx.y;
    extern __shared__ char sm[];
    ull  (*sX2)[HD] = (ull(*)[HD])sm;                 // [64][128] packed-dup
    ull  (*sH2)[HD] = (ull(*)[HD])(sm + 65536);       // [64][128] packed-dup
    float* sW       = (float*)(sm + 131072);          // [128][128]
    const int t = threadIdx.x;
    const int tx = t & 31, ty = t >> 5;
    const int c = tx * 4, r = ty * 8;

    // load WS tile (packed-dup) + W1
    #pragma unroll
    for (int it = 0; it < 16; it++) {
        int idx = t + it*256;                 // 0..4095 float2
        int row = idx >> 6, c2 = idx & 63;
        float2 v = *(const float2*)(g_ws + (size_t)k*NH + (size_t)(n0+row)*HD + c2*2);
        sX2[row][c2*2]   = pack2(v.x);
        sX2[row][c2*2+1] = pack2(v.y);
        ((float4*)sW)[idx] = ((const float4*)(W1 + (size_t)k*HD*HD))[idx];
    }
    __syncthreads();

    // ---- layer 1 ----
    ull acc[8][2];
    {
        ulonglong2 bv = *(const ulonglong2*)(b1 + (size_t)k*HD + c);
        #pragma unroll
        for (int i = 0; i < 8; i++) { acc[i][0] = bv.x; acc[i][1] = bv.y; }
    }
    #pragma unroll 4
    for (int kk = 0; kk < HD; kk++) {
        ulonglong2 w = *(const ulonglong2*)(sW + kk*HD + c);
        #pragma unroll
        for (int i = 0; i < 8; i++) {
            ull x = sX2[r+i][kk];
            ffma2(acc[i][0], x, w.x);
            ffma2(acc[i][1], x, w.y);
        }
    }
    #pragma unroll
    for (int i = 0; i < 8; i++) {
        float2 a = unpack2(acc[i][0]), b = unpack2(acc[i][1]);
        sH2[r+i][c]   = pack2(fmaxf(a.x, 0.f));
        sH2[r+i][c+1] = pack2(fmaxf(a.y, 0.f));
        sH2[r+i][c+2] = pack2(fmaxf(b.x, 0.f));
        sH2[r+i][c+3] = pack2(fmaxf(b.y, 0.f));
    }
    __syncthreads();
    // load W2 (overwrite sW)
    #pragma unroll
    for (int it = 0; it < 16; it++) {
        int idx = t + it*256;
        ((float4*)sW)[idx] = ((const float4*)(W2 + (size_t)k*HD*HD))[idx];
    }
    __syncthreads();

    // ---- layer 2 ----
    {
        ulonglong2 bv = *(const ulonglong2*)(b2 + (size_t)k*HD + c);
        #pragma unroll
        for (int i = 0; i < 8; i++) { acc[i][0] = bv.x; acc[i][1] = bv.y; }
    }
    #pragma unroll 4
    for (int kk = 0; kk < HD; kk++) {
        ulonglong2 w = *(const ulonglong2*)(sW + kk*HD + c);
        #pragma unroll
        for (int i = 0; i < 8; i++) {
            ull x = sH2[r+i][kk];
            ffma2(acc[i][0], x, w.x);
            ffma2(acc[i][1], x, w.y);
        }
    }
    #pragma unroll
    for (int i = 0; i < 8; i++) {
        float2 a = unpack2(acc[i][0]), b = unpack2(acc[i][1]);
        *(float4*)(g_hhat + (size_t)k*NH + (size_t)(n0+r+i)*HD + c) =
            make_float4(a.x, a.y, b.x, b.y);
    }
}

// ---------------- fused GRU: gi, gh, gates, H_next ----------------
// grid (256 ntiles of 32 rows, 32 k), 256 thr, dyn smem ~161KB
#define WST 388
__global__ __launch_bounds__(256, 1) void k_gru(const float* __restrict__ Wih,
                                                const float* __restrict__ Whh,
                                                const float* __restrict__ bhh,
                                                float* __restrict__ outH) {
    const int n0 = blockIdx.x * 32;
    const int k  = blockIdx.y;
    extern __shared__ char sm[];
    ull (*sD2)[HD] = (ull(*)[HD])sm;                 // [32][128] demb packed-dup
    ull (*sH2)[HD] = (ull(*)[HD])(sm + 32768);       // [32][128] hhat packed-dup
    float* sWi = (float*)(sm + 65536);               // [32][WST] kk-major
    float* sWh = sWi + 32*WST;
    const int t = threadIdx.x;
    const int tx = t & 63, ty = t >> 6;
    const int c = tx * 2, r0 = ty * 8;

    #pragma unroll
    for (int it = 0; it < 8; it++) {
        int idx = t + it*256;                        // 0..2047 float2
        int row = idx >> 6, c2 = idx & 63;
        float2 v1 = *(const float2*)(g_demb + (size_t)(n0+row)*HD + c2*2);
        sD2[row][c2*2]   = pack2(v1.x);
        sD2[row][c2*2+1] = pack2(v1.y);
        float2 v2 = *(const float2*)(g_hhat + (size_t)k*NH + (size_t)(n0+row)*HD + c2*2);
        sH2[row][c2*2]   = pack2(v2.x);
        sH2[row][c2*2+1] = pack2(v2.y);
    }

    ull ar[8], au[8], an[8], hr[8], hu[8], hn[8];
    {
        ull i0 = *(const ull*)(g_cih + k*G3 + c);
        ull i1 = *(const ull*)(g_cih + k*G3 + 128 + c);
        ull i2 = *(const ull*)(g_cih + k*G3 + 256 + c);
        ull h0 = *(const ull*)(bhh + k*G3 + c);
        ull h1 = *(const ull*)(bhh + k*G3 + 128 + c);
        ull h2 = *(const ull*)(bhh + k*G3 + 256 + c);
        #pragma unroll
        for (int i = 0; i < 8; i++) {
            ar[i] = i0; au[i] = i1; an[i] = i2;
            hr[i] = h0; hu[i] = h1; hn[i] = h2;
        }
    }
    const float* Wik = Wih + (size_t)k*G3*HD;
    const float* Whk = Whh + (size_t)k*G3*HD;

    for (int kc = 0; kc < 4; kc++) {
        __syncthreads();
        const int kk0 = kc * 32;
        #pragma unroll
        for (int it = 0; it < 12; it++) {
            int idx = t + it*256;                    // 0..3071
            int kk4 = idx & 7, m = idx >> 3;
            float4 a = *(const float4*)(Wik + (size_t)m*HD + kk0 + kk4*4);
            float4 b = *(const float4*)(Whk + (size_t)m*HD + kk0 + kk4*4);
            int kl = kk4 * 4;
            sWi[(kl+0)*WST + m] = a.x; sWi[(kl+1)*WST + m] = a.y;
            sWi[(kl+2)*WST + m] = a.z; sWi[(kl+3)*WST + m] = a.w;
            sWh[(kl+0)*WST + m] = b.x; sWh[(kl+1)*WST + m] = b.y;
            sWh[(kl+2)*WST + m] = b.z; sWh[(kl+3)*WST + m] = b.w;
        }
        __syncthreads();
        #pragma unroll 4
        for (int kk = 0; kk < 32; kk++) {
            ull wir = *(const ull*)(sWi + kk*WST + c);
            ull wiu = *(const ull*)(sWi + kk*WST + 128 + c);
            ull win = *(const ull*)(sWi + kk*WST + 256 + c);
            ull whr = *(const ull*)(sWh + kk*WST + c);
            ull whu = *(const ull*)(sWh + kk*WST + 128 + c);
            ull whn = *(const ull*)(sWh + kk*WST + 256 + c);
            #pragma unroll
            for (int i = 0; i < 8; i++) {
                ull xd = sD2[r0+i][kk0+kk];
                ull xh = sH2[r0+i][kk0+kk];
                ffma2(ar[i], xd, wir);
                ffma2(au[i], xd, wiu);
                ffma2(an[i], xd, win);
                ffma2(hr[i], xh, whr);
                ffma2(hu[i], xh, whu);
                ffma2(hn[i], xh, whn);
            }
        }
    }

    #pragma unroll
    for (int i = 0; i < 8; i++) {
        float2 vir = unpack2(ar[i]), vhr = unpack2(hr[i]);
        float2 viu = unpack2(au[i]), vhu = unpack2(hu[i]);
        float2 vin = unpack2(an[i]), vhn = unpack2(hn[i]);
        float hhx = unpack2(sH2[r0+i][c]).x;
        float hhy = unpack2(sH2[r0+i][c+1]).x;
        float rx = sigm(vir.x + vhr.x), ry = sigm(vir.y + vhr.y);
        float ux = sigm(viu.x + vhu.x), uy = sigm(viu.y + vhu.y);
        float nx = tanh_fast(vin.x + rx * vhn.x);
        float ny = tanh_fast(vin.y + ry * vhn.y);
        float2 o;
        o.x = (1.f - ux) * nx + ux * hhx;
        o.y = (1.f - uy) * ny + uy * hhy;
        *(float2*)(outH + ((size_t)k*NTOK + n0 + r0 + i)*HD + c) = o;
    }
}

// ---------------- reconstruction: [8192, 4096] @ [4096, 64] + b ----------------
// grid 128 (64-row tiles), 256 thr, dyn smem 96KB
__global__ __launch_bounds__(256, 1) void k_recon(const float* __restrict__ Hp,
                                                  const float* __restrict__ rW,
                                                  const float* __restrict__ rb,
                                                  float* __restrict__ outR) {
    const int n0 = blockIdx.x * 64;
    extern __shared__ char sm[];
    ull (*sX2)[HD] = (ull(*)[HD])sm;          // [64][128] packed-dup
    float* sWr = (float*)(sm + 65536);        // [128][64]
    const int t = threadIdx.x;
    const int tx = t & 31, ty = t >> 5;
    const int c = tx * 2, r0 = ty * 8;

    ull acc[8];
    {
        ull bv = *(const ull*)(rb + c);
        #pragma unroll
        for (int i = 0; i < 8; i++) acc[i] = bv;
    }

    for (int q = 0; q < QV; q++) {
        __syncthreads();
        #pragma unroll
        for (int it = 0; it < 16; it++) {
            int idx = t + it*256;             // 0..4095 float2
            int row = idx >> 6, c2 = idx & 63;
            float2 v = *(const float2*)(Hp + (size_t)q*NH + (size_t)(n0+row)*HD + c2*2);
            sX2[row][c2*2]   = pack2(v.x);
            sX2[row][c2*2+1] = pack2(v.y);
        }
        #pragma unroll
        for (int it = 0; it < 8; it++) {
            int idx = t + it*256;             // 0..2047 float4
            int row = idx >> 4, c4 = idx & 15;
            *(float4*)(sWr + row*RDIM + c4*4) =
                *(const float4*)(rW + ((size_t)q*HD + row)*RDIM + c4*4);
        }
        __syncthreads();
        #pragma unroll 4
        for (int kk = 0; kk < HD; kk++) {
            ull w = *(const ull*)(sWr + kk*RDIM + c);
            #pragma unroll
            for (int i = 0; i < 8; i++) ffma2(acc[i], sX2[r0+i][kk], w);
        }
    }
    #pragma unroll
    for (int i = 0; i < 8; i++) {
        float2 v = unpack2(acc[i]);
        *(float2*)(outR + (size_t)(n0 + r0 + i)*RDIM + c) = v;
    }
}

// ---------------- launch ----------------
extern "C" void kernel_launch(void* const* d_in, const int* in_sizes, int n_in,
                              void* d_out, int out_size) {
    const float* H_prev = (const float*)d_in[0];
    const float* driver = (const float*)d_in[1];
    const float* A_dag  = (const float*)d_in[2];
    const float* W1     = (const float*)d_in[3];
    const float* b1     = (const float*)d_in[4];
    const float* W2     = (const float*)d_in[5];
    const float* b2     = (const float*)d_in[6];
    const float* dW     = (const float*)d_in[7];
    const float* db     = (const float*)d_in[8];
    const float* Wih    = (const float*)d_in[9];
    const float* Whh    = (const float*)d_in[10];
    const float* bih    = (const float*)d_in[11];
    const float* bhh    = (const float*)d_in[12];
    const float* ve     = (const float*)d_in[13];
    const float* rW     = (const float*)d_in[14];
    const float* rb     = (const float*)d_in[15];

    float* outH = (float*)d_out;
    float* outR = outH + (size_t)QV * NTOK * HD;
    float* outA = outR + (size_t)NTOK * RDIM;

    cudaFuncSetAttribute(k_struct, cudaFuncAttributeMaxDynamicSharedMemorySize, 196608);
    cudaFuncSetAttribute(k_gru,    cudaFuncAttributeMaxDynamicSharedMemorySize, 65536 + 2*32*WST*4);
    cudaFuncSetAttribute(k_recon,  cudaFuncAttributeMaxDynamicSharedMemorySize, 98304);

    k_setup<<<QV, 128>>>(A_dag, Wih, bih, ve, outA);
    k_demb<<<NTOK/8, 128>>>(driver, dW, db);
    k_ws<<<NH/512, 256>>>(H_prev, A_dag);
    k_struct<<<dim3(NTOK/64, QV), 256, 196608>>>(W1, b1, W2, b2);
    k_gru<<<dim3(NTOK/32, QV), 256, 65536 + 2*32*WST*4>>>(Wih, Whh, bhh, outH);
    k_recon<<<NTOK/64, 256, 98304>>>(H_prev, rW, rb, outR);
}

// round 3
// speedup vs baseline: 1.2647x; 1.2647x over previous
#include <cuda_runtime.h>
#include <cstdint>

#define QV   32
#define NTOK 8192
#define HD   128
#define DD   64
#define RDIM 64
#define G3   384
#define NH   (NTOK*HD)   /* 1048576 */

typedef unsigned long long ull;

// ---------------- scratch (allocation-free) ----------------
__device__ float g_demb[NTOK*HD];       // 4 MB
__device__ float g_ws[QV*NTOK*HD];      // 128 MB
__device__ float g_hhat[QV*NTOK*HD];    // 128 MB
__device__ float g_cih[QV*G3];          // var_embed@W_ih + b_ih
__device__ float g_WihT[(size_t)QV*HD*G3];  // transposed [k][kk][m]
__device__ float g_WhhT[(size_t)QV*HD*G3];

// ---------------- f32x2 helpers ----------------
__device__ __forceinline__ ull pack2(float x) {
    ull r; unsigned xi = __float_as_uint(x);
    asm("mov.b64 %0, {%1, %1};" : "=l"(r) : "r"(xi));
    return r;
}
__device__ __forceinline__ float2 unpack2(ull v) {
    unsigned lo, hi;
    asm("mov.b64 {%0, %1}, %2;" : "=r"(lo), "=r"(hi) : "l"(v));
    return make_float2(__uint_as_float(lo), __uint_as_float(hi));
}
__device__ __forceinline__ void ffma2(ull &d, ull a, ull b) {
    asm("fma.rn.f32x2 %0, %1, %2, %0;" : "+l"(d) : "l"(a), "l"(b));
}
__device__ __forceinline__ ull add2(ull a, ull b) {
    ull r; asm("add.rn.f32x2 %0, %1, %2;" : "=l"(r) : "l"(a), "l"(b));
    return r;
}
__device__ __forceinline__ float sigm(float x) { return 1.f / (1.f + __expf(-x)); }
__device__ __forceinline__ float tanh_fast(float x) {
    float a = fabsf(x);
    float e = __expf(-2.f * a);
    float t = (1.f - e) / (1.f + e);
    return copysignf(t, x);
}

// ---------------- cp.async helpers ----------------
__device__ __forceinline__ void cp_async16(uint32_t smem_addr, const void* gptr) {
    asm volatile("cp.async.cg.shared.global [%0], [%1], 16;"
                 :: "r"(smem_addr), "l"(gptr) : "memory");
}
__device__ __forceinline__ void cp_commit() {
    asm volatile("cp.async.commit_group;" ::: "memory");
}
__device__ __forceinline__ void cp_wait0() {
    asm volatile("cp.async.wait_group 0;" ::: "memory");
}

// ---------------- setup: c_ih = var_embed @ W_ih^T + b_ih ; A_masked out ----------------
__global__ void k_setup(const float* __restrict__ A_dag, const float* __restrict__ Wih,
                        const float* __restrict__ bih, const float* __restrict__ ve,
                        float* __restrict__ outA) {
    int k = blockIdx.x, t = threadIdx.x;
    __shared__ float sve[HD];
    sve[t] = ve[k*HD + t];
    __syncthreads();
    for (int m = t; m < G3; m += 128) {
        const float* w = Wih + ((size_t)k*G3 + m)*HD;
        float acc = bih[k*G3 + m];
        #pragma unroll 8
        for (int j = 0; j < HD; j++) acc += sve[j] * w[j];
        g_cih[k*G3 + m] = acc;
    }
    if (k == 0) {
        for (int idx = t; idx < QV*QV; idx += 128) {
            int i = idx / QV, j = idx % QV;
            outA[idx] = (i == j) ? 0.f : A_dag[idx];
        }
    }
}

// ---------------- transpose GRU weights: [k][m][kk] -> [k][kk][m] ----------------
// grid (48, 32, 2): 12 m-tiles x 4 kk-tiles, k, mat; 256 threads
__global__ void k_wtr(const float* __restrict__ Wih, const float* __restrict__ Whh) {
    __shared__ float tile[32][33];
    int k = blockIdx.y;
    int mt = blockIdx.x / 4, kt = blockIdx.x % 4;
    const float* src = blockIdx.z ? Whh : Wih;
    float* dst = blockIdx.z ? g_WhhT : g_WihT;
    int tx = threadIdx.x & 31, ty = threadIdx.x >> 5;   // ty 0..7
    #pragma unroll
    for (int i = 0; i < 32; i += 8)
        tile[ty+i][tx] = src[((size_t)k*G3 + mt*32 + ty+i)*HD + kt*32 + tx];
    __syncthreads();
    #pragma unroll
    for (int i = 0; i < 32; i += 8)
        dst[((size_t)k*HD + kt*32 + ty+i)*G3 + mt*32 + tx] = tile[tx][ty+i];
}

// ---------------- driver_emb = relu(driver @ driver_W + b) ----------------
__global__ void k_demb(const float* __restrict__ driver, const float* __restrict__ dW,
                       const float* __restrict__ db) {
    __shared__ float sdrv[8][DD];
    int n0 = blockIdx.x * 8, t = threadIdx.x;
    for (int i = t; i < 8*DD; i += 128)
        sdrv[i/DD][i%DD] = driver[(size_t)(n0 + i/DD)*DD + (i%DD)];
    __syncthreads();
    float acc[8];
    float b = db[t];
    #pragma unroll
    for (int r = 0; r < 8; r++) acc[r] = b;
    #pragma unroll 4
    for (int d = 0; d < DD; d++) {
        float w = dW[d*HD + t];
        #pragma unroll
        for (int r = 0; r < 8; r++) acc[r] += sdrv[r][d] * w;
    }
    #pragma unroll
    for (int r = 0; r < 8; r++)
        g_demb[(size_t)(n0 + r)*HD + t] = fmaxf(acc[r], 0.f);
}

// ---------------- ws[k,n,j] = sum_i A_masked[i,k] * H_prev[i,n,j] ----------------
__global__ __launch_bounds__(256) void k_ws(const float* __restrict__ Hp,
                                            const float* __restrict__ A_dag) {
    __shared__ ull sA[QV][QV];       // packed-duplicated A_masked[i][k]
    int t = threadIdx.x;
    for (int idx = t; idx < QV*QV; idx += 256) {
        int i = idx / QV, kk = idx % QV;
        float v = (i == kk) ? 0.f : A_dag[idx];
        sA[i][kk] = pack2(v);
    }
    __syncthreads();
    size_t p = ((size_t)blockIdx.x * 256 + t) * 2;
    ull acc[QV];
    #pragma unroll
    for (int kk = 0; kk < QV; kk++) acc[kk] = 0ull;
    #pragma unroll 4
    for (int i = 0; i < QV; i++) {
        ull h = *(const ull*)(Hp + (size_t)i*NH + p);
        #pragma unroll
        for (int kk = 0; kk < QV; kk++) ffma2(acc[kk], sA[i][kk], h);
    }
    #pragma unroll
    for (int kk = 0; kk < QV; kk++)
        *(ull*)(g_ws + (size_t)kk*NH + p) = acc[kk];
}

// ---------------- struct MLP: Hhat = (relu(WS@W1+b1))@W2 + b2, per k ----------------
// grid (64 ntiles of 128 rows, 32 k), 512 thr, dyn smem 192KB
__global__ __launch_bounds__(512, 1) void k_struct(const float* __restrict__ W1,
                                                   const float* __restrict__ b1,
                                                   const float* __restrict__ W2,
                                                   const float* __restrict__ b2) {
    const int n0 = blockIdx.x * 128;
    const int k  = blockIdx.y;
    extern __shared__ char sm[];
    ull  (*sX2)[HD] = (ull(*)[HD])sm;                 // [128][128] packed-dup (X, then H)
    float* sW       = (float*)(sm + 131072);          // [128][128]
    const int t = threadIdx.x;
    const int tx = t & 31, ty = t >> 5;               // tx 0..31, ty 0..15
    const int c = tx * 4, r = ty * 8;

    // load WS tile (packed-dup) + W1
    #pragma unroll
    for (int it = 0; it < 16; it++) {
        int idx = t + it*512;                 // 0..8191 float2
        int row = idx >> 6, c2 = idx & 63;
        float2 v = *(const float2*)(g_ws + (size_t)k*NH + (size_t)(n0+row)*HD + c2*2);
        sX2[row][c2*2]   = pack2(v.x);
        sX2[row][c2*2+1] = pack2(v.y);
    }
    #pragma unroll
    for (int it = 0; it < 8; it++) {
        int idx = t + it*512;                 // 0..4095 float4
        ((float4*)sW)[idx] = ((const float4*)(W1 + (size_t)k*HD*HD))[idx];
    }
    __syncthreads();

    // ---- layer 1 ----
    ull acc[8][2];
    {
        ulonglong2 bv = *(const ulonglong2*)(b1 + (size_t)k*HD + c);
        #pragma unroll
        for (int i = 0; i < 8; i++) { acc[i][0] = bv.x; acc[i][1] = bv.y; }
    }
    #pragma unroll 2
    for (int kkp = 0; kkp < 64; kkp++) {
        ulonglong2 w0 = *(const ulonglong2*)(sW + (2*kkp)*HD + c);
        ulonglong2 w1 = *(const ulonglong2*)(sW + (2*kkp+1)*HD + c);
        #pragma unroll
        for (int i = 0; i < 8; i++) {
            ulonglong2 xv = *(const ulonglong2*)&sX2[r+i][2*kkp];
            ffma2(acc[i][0], xv.x, w0.x);
            ffma2(acc[i][1], xv.x, w0.y);
            ffma2(acc[i][0], xv.y, w1.x);
            ffma2(acc[i][1], xv.y, w1.y);
        }
    }
    __syncthreads();   // all reads of X and W1 done

    // store relu(H1) back into sX2 (X is dead); load W2 over W1
    #pragma unroll
    for (int i = 0; i < 8; i++) {
        float2 a = unpack2(acc[i][0]), b = unpack2(acc[i][1]);
        sX2[r+i][c]   = pack2(fmaxf(a.x, 0.f));
        sX2[r+i][c+1] = pack2(fmaxf(a.y, 0.f));
        sX2[r+i][c+2] = pack2(fmaxf(b.x, 0.f));
        sX2[r+i][c+3] = pack2(fmaxf(b.y, 0.f));
    }
    #pragma unroll
    for (int it = 0; it < 8; it++) {
        int idx = t + it*512;
        ((float4*)sW)[idx] = ((const float4*)(W2 + (size_t)k*HD*HD))[idx];
    }
    __syncthreads();

    // ---- layer 2 ----
    {
        ulonglong2 bv = *(const ulonglong2*)(b2 + (size_t)k*HD + c);
        #pragma unroll
        for (int i = 0; i < 8; i++) { acc[i][0] = bv.x; acc[i][1] = bv.y; }
    }
    #pragma unroll 2
    for (int kkp = 0; kkp < 64; kkp++) {
        ulonglong2 w0 = *(const ulonglong2*)(sW + (2*kkp)*HD + c);
        ulonglong2 w1 = *(const ulonglong2*)(sW + (2*kkp+1)*HD + c);
        #pragma unroll
        for (int i = 0; i < 8; i++) {
            ulonglong2 xv = *(const ulonglong2*)&sX2[r+i][2*kkp];
            ffma2(acc[i][0], xv.x, w0.x);
            ffma2(acc[i][1], xv.x, w0.y);
            ffma2(acc[i][0], xv.y, w1.x);
            ffma2(acc[i][1], xv.y, w1.y);
        }
    }
    #pragma unroll
    for (int i = 0; i < 8; i++) {
        float2 a = unpack2(acc[i][0]), b = unpack2(acc[i][1]);
        *(float4*)(g_hhat + (size_t)k*NH + (size_t)(n0+r+i)*HD + c) =
            make_float4(a.x, a.y, b.x, b.y);
    }
}

// ---------------- fused GRU ----------------
// grid (128 ntiles of 64 rows, 32 k), 512 thr, dyn smem 224KB
// smem: sDH ull[64][256] interleaved {demb,hhat} dup (131072B), then
//       weight chunks [2 bufs][2 mats][16 kk][384 m] floats (4*24576B)
__global__ __launch_bounds__(512, 1) void k_gru(const float* __restrict__ bhh,
                                                float* __restrict__ outH) {
    const int n0 = blockIdx.x * 64;
    const int k  = blockIdx.y;
    extern __shared__ char sm[];
    ull (*sDH)[256] = (ull(*)[256])sm;
    const int t = threadIdx.x;
    const int tx = t & 63, ty = t >> 6;         // tx 0..63, ty 0..7
    const int c = tx * 2, r0 = ty * 8;
    uint32_t wbs = (uint32_t)__cvta_generic_to_shared(sm + 131072);
    const float* WiT = g_WihT + (size_t)k*HD*G3;
    const float* WhT = g_WhhT + (size_t)k*HD*G3;

    // prefetch weight chunk 0 into buf 0 (overlaps with activation loads)
    #pragma unroll
    for (int it = 0; it < 3; it++) {
        int idx = t + it*512;                   // 0..1535 float4
        cp_async16(wbs + 0*24576 + idx*16, WiT + idx*4);
        cp_async16(wbs + 1*24576 + idx*16, WhT + idx*4);
    }
    cp_commit();

    // load activations interleaved + duplicated
    #pragma unroll
    for (int it = 0; it < 8; it++) {
        int idx = t + it*512;                   // 0..4095 float2
        int row = idx >> 6, c2 = idx & 63;
        float2 v1 = *(const float2*)(g_demb + (size_t)(n0+row)*HD + c2*2);
        float2 v2 = *(const float2*)(g_hhat + (size_t)k*NH + (size_t)(n0+row)*HD + c2*2);
        sDH[row][c2*4 + 0] = pack2(v1.x);
        sDH[row][c2*4 + 1] = pack2(v2.x);
        sDH[row][c2*4 + 2] = pack2(v1.y);
        sDH[row][c2*4 + 3] = pack2(v2.y);
    }

    // accumulators: r/u gates merged (i_r + h_r share one accumulator)
    ull ar[8], au[8], an[8], hn[8];
    {
        ull i0 = *(const ull*)(g_cih + k*G3 + c);
        ull i1 = *(const ull*)(g_cih + k*G3 + 128 + c);
        ull i2 = *(const ull*)(g_cih + k*G3 + 256 + c);
        ull h0 = *(const ull*)(bhh + k*G3 + c);
        ull h1 = *(const ull*)(bhh + k*G3 + 128 + c);
        ull h2 = *(const ull*)(bhh + k*G3 + 256 + c);
        ull ir = add2(i0, h0), iu = add2(i1, h1);
        #pragma unroll
        for (int i = 0; i < 8; i++) { ar[i] = ir; au[i] = iu; an[i] = i2; hn[i] = h2; }
    }

    for (int ch = 0; ch < 8; ch++) {
        cp_wait0();
        __syncthreads();
        if (ch < 7) {
            int b = (ch + 1) & 1;
            const float* si = WiT + (size_t)(ch+1)*6144;
            const float* sh = WhT + (size_t)(ch+1)*6144;
            #pragma unroll
            for (int it = 0; it < 3; it++) {
                int idx = t + it*512;
                cp_async16(wbs + (b*2+0)*24576 + idx*16, si + idx*4);
                cp_async16(wbs + (b*2+1)*24576 + idx*16, sh + idx*4);
            }
            cp_commit();
        }
        const float* wi = (float*)(sm + 131072 + ((ch&1)*2+0)*24576);
        const float* wh = (float*)(sm + 131072 + ((ch&1)*2+1)*24576);
        const int kg0 = ch * 16;
        #pragma unroll 4
        for (int kk = 0; kk < 16; kk++) {
            ull wir = *(const ull*)(wi + kk*G3 + c);
            ull wiu = *(const ull*)(wi + kk*G3 + 128 + c);
            ull win = *(const ull*)(wi + kk*G3 + 256 + c);
            ull whr = *(const ull*)(wh + kk*G3 + c);
            ull whu = *(const ull*)(wh + kk*G3 + 128 + c);
            ull whn = *(const ull*)(wh + kk*G3 + 256 + c);
            const int kg = (kg0 + kk) * 2;
            #pragma unroll
            for (int i = 0; i < 8; i++) {
                ulonglong2 xv = *(const ulonglong2*)&sDH[r0+i][kg]; // {demb, hhat}
                ffma2(ar[i], xv.x, wir);
                ffma2(ar[i], xv.y, whr);
                ffma2(au[i], xv.x, wiu);
                ffma2(au[i], xv.y, whu);
                ffma2(an[i], xv.x, win);
                ffma2(hn[i], xv.y, whn);
            }
        }
    }

    #pragma unroll
    for (int i = 0; i < 8; i++) {
        float2 vr = unpack2(ar[i]);
        float2 vu = unpack2(au[i]);
        float2 vin = unpack2(an[i]);
        float2 vhn = unpack2(hn[i]);
        float hhx = unpack2(sDH[r0+i][c*2 + 1]).x;
        float hhy = unpack2(sDH[r0+i][c*2 + 3]).x;
        float rx = sigm(vr.x), ry = sigm(vr.y);
        float ux = sigm(vu.x), uy = sigm(vu.y);
        float nx = tanh_fast(vin.x + rx * vhn.x);
        float ny = tanh_fast(vin.y + ry * vhn.y);
        float2 o;
        o.x = (1.f - ux) * nx + ux * hhx;
        o.y = (1.f - uy) * ny + uy * hhy;
        *(float2*)(outH + ((size_t)k*NTOK + n0 + r0 + i)*HD + c) = o;
    }
}

// ---------------- reconstruction: [8192, 4096] @ [4096, 64] + b ----------------
// grid 128 (64-row tiles), 256 thr, dyn smem 96KB
__global__ __launch_bounds__(256, 1) void k_recon(const float* __restrict__ Hp,
                                                  const float* __restrict__ rW,
                                                  const float* __restrict__ rb,
                                                  float* __restrict__ outR) {
    const int n0 = blockIdx.x * 64;
    extern __shared__ char sm[];
    ull (*sX2)[HD] = (ull(*)[HD])sm;          // [64][128] packed-dup
    float* sWr = (float*)(sm + 65536);        // [128][64]
    const int t = threadIdx.x;
    const int tx = t & 31, ty = t >> 5;
    const int c = tx * 2, r0 = ty * 8;

    ull acc[8];
    {
        ull bv = *(const ull*)(rb + c);
        #pragma unroll
        for (int i = 0; i < 8; i++) acc[i] = bv;
    }

    for (int q = 0; q < QV; q++) {
        __syncthreads();
        #pragma unroll
        for (int it = 0; it < 16; it++) {
            int idx = t + it*256;             // 0..4095 float2
            int row = idx >> 6, c2 = idx & 63;
            float2 v = *(const float2*)(Hp + (size_t)q*NH + (size_t)(n0+row)*HD + c2*2);
            sX2[row][c2*2]   = pack2(v.x);
            sX2[row][c2*2+1] = pack2(v.y);
        }
        #pragma unroll
        for (int it = 0; it < 8; it++) {
            int idx = t + it*256;             // 0..2047 float4
            int row = idx >> 4, c4 = idx & 15;
            *(float4*)(sWr + row*RDIM + c4*4) =
                *(const float4*)(rW + ((size_t)q*HD + row)*RDIM + c4*4);
        }
        __syncthreads();
        #pragma unroll 4
        for (int kk = 0; kk < HD; kk++) {
            ull w = *(const ull*)(sWr + kk*RDIM + c);
            #pragma unroll
            for (int i = 0; i < 8; i++) ffma2(acc[i], sX2[r0+i][kk], w);
        }
    }
    #pragma unroll
    for (int i = 0; i < 8; i++) {
        float2 v = unpack2(acc[i]);
        *(float2*)(outR + (size_t)(n0 + r0 + i)*RDIM + c) = v;
    }
}

// ---------------- launch ----------------
extern "C" void kernel_launch(void* const* d_in, const int* in_sizes, int n_in,
                              void* d_out, int out_size) {
    const float* H_prev = (const float*)d_in[0];
    const float* driver = (const float*)d_in[1];
    const float* A_dag  = (const float*)d_in[2];
    const float* W1     = (const float*)d_in[3];
    const float* b1     = (const float*)d_in[4];
    const float* W2     = (const float*)d_in[5];
    const float* b2     = (const float*)d_in[6];
    const float* dW     = (const float*)d_in[7];
    const float* db     = (const float*)d_in[8];
    const float* Wih    = (const float*)d_in[9];
    const float* Whh    = (const float*)d_in[10];
    const float* bih    = (const float*)d_in[11];
    const float* bhh    = (const float*)d_in[12];
    const float* ve     = (const float*)d_in[13];
    const float* rW     = (const float*)d_in[14];
    const float* rb     = (const float*)d_in[15];

    float* outH = (float*)d_out;
    float* outR = outH + (size_t)QV * NTOK * HD;
    float* outA = outR + (size_t)NTOK * RDIM;

    cudaFuncSetAttribute(k_struct, cudaFuncAttributeMaxDynamicSharedMemorySize, 196608);
    cudaFuncSetAttribute(k_gru,    cudaFuncAttributeMaxDynamicSharedMemorySize, 229376);
    cudaFuncSetAttribute(k_recon,  cudaFuncAttributeMaxDynamicSharedMemorySize, 98304);

    k_setup<<<QV, 128>>>(A_dag, Wih, bih, ve, outA);
    k_wtr<<<dim3(48, QV, 2), 256>>>(Wih, Whh);
    k_demb<<<NTOK/8, 128>>>(driver, dW, db);
    k_ws<<<NH/512, 256>>>(H_prev, A_dag);
    k_struct<<<dim3(NTOK/128, QV), 512, 196608>>>(W1, b1, W2, b2);
    k_gru<<<dim3(NTOK/64, QV), 512, 229376>>>(bhh, outH);
    k_recon<<<NTOK/64, 256, 98304>>>(H_prev, rW, rb, outR);
}